// round 1
// baseline (speedup 1.0000x reference)
#include <cuda_runtime.h>
#include <math.h>

#define BB    4
#define NTOK  4096
#define CDIM  1024
#define HH    4
#define DH    256
#define BHN   (BB*HH)        /* 16 */
#define EPSV   1e-5f
#define SCALEV 0.03125f      /* 1/sqrt(1024) */

// ---------------- scratch (device globals; no allocation) ----------------
__device__ __align__(16) float g_Q  [(size_t)BB*HH*NTOK*DH];
__device__ __align__(16) float g_Qd [(size_t)BB*HH*NTOK*DH];
__device__ __align__(16) float g_K  [(size_t)BB*HH*NTOK*DH];
__device__ __align__(16) float g_V  [(size_t)BB*HH*NTOK*DH];
__device__ __align__(16) float g_Kd [(size_t)BB*HH*NTOK*DH];
__device__ __align__(16) float g_Vd [(size_t)BB*HH*NTOK*DH];
__device__ __align__(16) float g_s1 [(size_t)BHN*DH*DH];
__device__ __align__(16) float g_sd1[(size_t)BHN*DH*DH];
__device__ __align__(16) float g_ctx1 [(size_t)BB*NTOK*CDIM];
__device__ __align__(16) float g_ctxd1[(size_t)BB*NTOK*CDIM];
__device__ float g_mv[2*BHN*2];   // [path][bh][{mean,var}]

// ---------------- 64x64 tile compute core (4x4 per thread) ----------------
__device__ __forceinline__ void mma16(const float (*As)[64], const float (*Ws)[64],
                                      int tx, int ty, float acc[4][4])
{
#pragma unroll
    for (int kk = 0; kk < 16; ++kk) {
        float4 a4 = *reinterpret_cast<const float4*>(&As[kk][ty*4]);
        float4 b4 = *reinterpret_cast<const float4*>(&Ws[kk][tx*4]);
        float av[4] = {a4.x, a4.y, a4.z, a4.w};
        float bv[4] = {b4.x, b4.y, b4.z, b4.w};
#pragma unroll
        for (int i = 0; i < 4; ++i)
#pragma unroll
            for (int j = 0; j < 4; ++j)
                acc[i][j] = fmaf(av[i], bv[j], acc[i][j]);
    }
}

// C[m,n] = sum_k A[m,k] * W[n,k]   (both row-major, NT). A/W pre-offset to tile origin.
__device__ __forceinline__ void gemm64_nt_body(const float* __restrict__ A, int lda,
                                               const float* __restrict__ W, int ldw,
                                               int K, float acc[4][4])
{
    __shared__ float As[16][64];
    __shared__ float Ws[16][64];
    const int tid = threadIdx.x;
    const int tx = tid & 15, ty = tid >> 4;
    const int lm = tid >> 2;          // 0..63
    const int lk = (tid & 3) * 4;     // 0,4,8,12
    for (int k0 = 0; k0 < K; k0 += 16) {
        float4 va = *reinterpret_cast<const float4*>(A + (size_t)lm*lda + k0 + lk);
        float4 vw = *reinterpret_cast<const float4*>(W + (size_t)lm*ldw + k0 + lk);
        As[lk+0][lm] = va.x; As[lk+1][lm] = va.y; As[lk+2][lm] = va.z; As[lk+3][lm] = va.w;
        Ws[lk+0][lm] = vw.x; Ws[lk+1][lm] = vw.y; Ws[lk+2][lm] = vw.z; Ws[lk+3][lm] = vw.w;
        __syncthreads();
        mma16(As, Ws, tx, ty, acc);
        __syncthreads();
    }
}

// C[c,k] = sum_n A[n,c] * B[n,k]   (TN: contract leading dim). A/B pre-offset to col origin.
__device__ __forceinline__ void gemm64_tn_body(const float* __restrict__ A, int lda,
                                               const float* __restrict__ Bm, int ldb,
                                               int K, float acc[4][4])
{
    __shared__ float As[16][64];
    __shared__ float Bs[16][64];
    const int tid = threadIdx.x;
    const int tx = tid & 15, ty = tid >> 4;
    const int lr = tid >> 4;          // 0..15 (k-step row)
    const int lc = (tid & 15) * 4;    // 0..60
    for (int k0 = 0; k0 < K; k0 += 16) {
        *reinterpret_cast<float4*>(&As[lr][lc]) =
            *reinterpret_cast<const float4*>(A  + (size_t)(k0+lr)*lda + lc);
        *reinterpret_cast<float4*>(&Bs[lr][lc]) =
            *reinterpret_cast<const float4*>(Bm + (size_t)(k0+lr)*ldb + lc);
        __syncthreads();
        mma16(As, Bs, tx, ty, acc);
        __syncthreads();
    }
}

// ---------------- stage kernels ----------------

// which: 0 Q, 1 Qd, 2 K, 3 V, 4 Kd, 5 Vd
__global__ void __launch_bounds__(256) k_proj(const float* __restrict__ in,
                                              const float* __restrict__ W,
                                              int which, int perHead)
{
    float* out = (which == 0) ? g_Q  : (which == 1) ? g_Qd :
                 (which == 2) ? g_K  : (which == 3) ? g_V  :
                 (which == 4) ? g_Kd : g_Vd;
    const int bh = blockIdx.z;
    const int b = bh >> 2, h = bh & 3;
    const int n0 = blockIdx.x * 64, o0 = blockIdx.y * 64;
    const float* A  = in + ((size_t)b*NTOK + n0)*CDIM + h*DH;
    const float* Wp = W + (perHead ? (size_t)h*DH*DH : 0) + (size_t)o0*DH;
    float acc[4][4] = {};
    gemm64_nt_body(A, CDIM, Wp, DH, DH, acc);
    const int tx = threadIdx.x & 15, ty = threadIdx.x >> 4;
    float* O = out + ((size_t)bh*NTOK + n0)*DH + o0;
#pragma unroll
    for (int i = 0; i < 4; ++i) {
        float4 v = make_float4(acc[i][0], acc[i][1], acc[i][2], acc[i][3]);
        *reinterpret_cast<float4*>(O + (size_t)(ty*4+i)*DH + tx*4) = v;
    }
}

// which 0: s1 = scale * Q^T Kd ; which 1: sd1 = scale * Qd^T K
__global__ void __launch_bounds__(256) k_score(int which)
{
    const float* Am = which ? g_Qd : g_Q;
    const float* Bm = which ? g_K  : g_Kd;
    float*       S  = which ? g_sd1 : g_s1;
    const int bh = blockIdx.z;
    const int c0 = blockIdx.y * 64, kk0 = blockIdx.x * 64;
    const float* Ap = Am + (size_t)bh*NTOK*DH + c0;
    const float* Bp = Bm + (size_t)bh*NTOK*DH + kk0;
    float acc[4][4] = {};
    gemm64_tn_body(Ap, DH, Bp, DH, NTOK, acc);
    const int tx = threadIdx.x & 15, ty = threadIdx.x >> 4;
    float* Sp = S + (size_t)bh*DH*DH + (size_t)c0*DH + kk0;
#pragma unroll
    for (int i = 0; i < 4; ++i) {
        float4 v = make_float4(acc[i][0]*SCALEV, acc[i][1]*SCALEV,
                               acc[i][2]*SCALEV, acc[i][3]*SCALEV);
        *reinterpret_cast<float4*>(Sp + (size_t)(ty*4+i)*DH + tx*4) = v;
    }
}

// per (path, bh): mean & var over the 256x256 score plane
__global__ void __launch_bounds__(256) k_moments()
{
    const int idx = blockIdx.x;                 // 0..31
    const float* s = (idx < BHN ? g_s1 : g_sd1) + (size_t)(idx & 15)*DH*DH;
    __shared__ float sh[256], sh2[256];
    float sum = 0.f, sq = 0.f;
    for (int i = threadIdx.x; i < DH*DH; i += 256) {
        float v = s[i];
        sum += v; sq = fmaf(v, v, sq);
    }
    sh[threadIdx.x] = sum; sh2[threadIdx.x] = sq;
    __syncthreads();
    for (int o = 128; o; o >>= 1) {
        if (threadIdx.x < o) { sh[threadIdx.x] += sh[threadIdx.x+o]; sh2[threadIdx.x] += sh2[threadIdx.x+o]; }
        __syncthreads();
    }
    if (threadIdx.x == 0) {
        float m   = sh[0]  * (1.f/65536.f);
        float var = sh2[0] * (1.f/65536.f) - m*m;
        g_mv[idx*2]   = m;
        g_mv[idx*2+1] = var;
    }
}

// instance-norm (per bh moments) + row softmax over k (256), in-place
__global__ void __launch_bounds__(256) k_softmax()
{
    const int path = blockIdx.z;
    const int bh   = blockIdx.y;
    const int c    = blockIdx.x;
    float* row = (path ? g_sd1 : g_s1) + ((size_t)bh*DH + c)*DH;
    const int mvi = path*BHN + bh;
    const float mean = g_mv[mvi*2];
    const float inv  = rsqrtf(g_mv[mvi*2+1] + EPSV);
    const int tid = threadIdx.x;
    float y = (row[tid] - mean) * inv;

    __shared__ float red[8];
    float m = y;
#pragma unroll
    for (int o = 16; o; o >>= 1) m = fmaxf(m, __shfl_xor_sync(0xffffffffu, m, o));
    if ((tid & 31) == 0) red[tid >> 5] = m;
    __syncthreads();
    if (tid == 0) {
        float mm = red[0];
        for (int i = 1; i < 8; ++i) mm = fmaxf(mm, red[i]);
        red[0] = mm;
    }
    __syncthreads();
    float e = expf(y - red[0]);
    __syncthreads();
    float s = e;
#pragma unroll
    for (int o = 16; o; o >>= 1) s += __shfl_xor_sync(0xffffffffu, s, o);
    if ((tid & 31) == 0) red[tid >> 5] = s;
    __syncthreads();
    if (tid == 0) {
        float t = 0.f;
        for (int i = 0; i < 8; ++i) t += red[i];
        red[0] = t;
    }
    __syncthreads();
    row[tid] = e / red[0];
}

// which 0: ctx1[b,n,c*4+h] = sum_k p1 * Vd ; which 1: ctxd1 with (sd1, V)
__global__ void __launch_bounds__(256) k_ctx(int which)
{
    const float* Vm = which ? g_V   : g_Vd;
    const float* P  = which ? g_sd1 : g_s1;
    float*      ctx = which ? g_ctxd1 : g_ctx1;
    const int bh = blockIdx.z, b = bh >> 2, h = bh & 3;
    const int n0 = blockIdx.x * 64, c0 = blockIdx.y * 64;
    const float* A = Vm + ((size_t)bh*NTOK + n0)*DH;
    const float* W = P  + (size_t)bh*DH*DH + (size_t)c0*DH;
    float acc[4][4] = {};
    gemm64_nt_body(A, DH, W, DH, DH, acc);
    const int tx = threadIdx.x & 15, ty = threadIdx.x >> 4;
    float* O = ctx + ((size_t)b*NTOK + n0)*CDIM + h;
#pragma unroll
    for (int i = 0; i < 4; ++i)
#pragma unroll
        for (int j = 0; j < 4; ++j)
            O[(size_t)(ty*4+i)*CDIM + (size_t)(c0 + tx*4 + j)*4] = acc[i][j];
}

// O = ctx @ Wout^T  (M = B*N flat)
__global__ void __launch_bounds__(256) k_out(const float* __restrict__ W,
                                             float* __restrict__ O, int which)
{
    const float* ctx = which ? g_ctxd1 : g_ctx1;
    const int m0 = blockIdx.x * 64, j0 = blockIdx.y * 64;
    const float* A  = ctx + (size_t)m0*CDIM;
    const float* Wp = W   + (size_t)j0*CDIM;
    float acc[4][4] = {};
    gemm64_nt_body(A, CDIM, Wp, CDIM, CDIM, acc);
    const int tx = threadIdx.x & 15, ty = threadIdx.x >> 4;
    float* Op = O + (size_t)m0*CDIM + j0;
#pragma unroll
    for (int i = 0; i < 4; ++i) {
        float4 v = make_float4(acc[i][0], acc[i][1], acc[i][2], acc[i][3]);
        *reinterpret_cast<float4*>(Op + (size_t)(ty*4+i)*CDIM + tx*4) = v;
    }
}

// ---------------- launch ----------------
extern "C" void kernel_launch(void* const* d_in, const int* in_sizes, int n_in,
                              void* d_out, int out_size)
{
    const float* emb1     = (const float*)d_in[0];
    const float* emb_all  = (const float*)d_in[1];
    const float* embd1    = (const float*)d_in[2];
    const float* emb_alld = (const float*)d_in[3];
    const float* Wq    = (const float*)d_in[4];
    const float* Wqd   = (const float*)d_in[5];
    const float* Wk0   = (const float*)d_in[6];
    const float* Wv0   = (const float*)d_in[7];
    const float* Wkd0  = (const float*)d_in[8];
    const float* Wvd0  = (const float*)d_in[9];
    const float* Wout  = (const float*)d_in[10];
    const float* Woutd = (const float*)d_in[11];
    float* out = (float*)d_out;

    dim3 gp(NTOK/64, DH/64, BHN);
    k_proj<<<gp, 256>>>(emb1,     Wq,   0, 1);
    k_proj<<<gp, 256>>>(embd1,    Wqd,  1, 1);
    k_proj<<<gp, 256>>>(emb_all,  Wk0,  2, 0);
    k_proj<<<gp, 256>>>(emb_all,  Wv0,  3, 0);
    k_proj<<<gp, 256>>>(emb_alld, Wkd0, 4, 0);
    k_proj<<<gp, 256>>>(emb_alld, Wvd0, 5, 0);

    dim3 gs(DH/64, DH/64, BHN);
    k_score<<<gs, 256>>>(0);
    k_score<<<gs, 256>>>(1);

    k_moments<<<32, 256>>>();
    k_softmax<<<dim3(DH, BHN, 2), 256>>>();

    dim3 gc(NTOK/64, DH/64, BHN);
    k_ctx<<<gc, 256>>>(0);
    k_ctx<<<gc, 256>>>(1);

    dim3 go(BB*NTOK/64, CDIM/64);
    k_out<<<go, 256>>>(Wout,  out, 0);
    k_out<<<go, 256>>>(Woutd, out + (size_t)BB*NTOK*CDIM, 1);
}